// round 4
// baseline (speedup 1.0000x reference)
#include <cuda_runtime.h>
#include <cuda_bf16.h>
#include <cstdint>

#define B_  4
#define L_  1024
#define H_  1024
#define NH_ 16
#define HD_ 64
#define M_  (B_*L_)   // 4096
#define LOG2E 1.4426950408889634f

// ---------------- scratch (device globals; no runtime alloc) ----------------
__device__ float g_Q  [M_ * H_];
__device__ float g_KVs[M_ * 2 * H_];
__device__ float g_KVl[M_ * 2 * H_];
__device__ float g_mix[M_ * H_];
__device__ __nv_bfloat16 g_xhi[M_ * H_],  g_xlo[M_ * H_];
__device__ __nv_bfloat16 g_mhi[M_ * H_],  g_mlo[M_ * H_];
__device__ __nv_bfloat16 g_Wqt_hi[H_ * H_],     g_Wqt_lo[H_ * H_];
__device__ __nv_bfloat16 g_Wst_hi[2 * H_ * H_], g_Wst_lo[2 * H_ * H_];
__device__ __nv_bfloat16 g_Wlt_hi[2 * H_ * H_], g_Wlt_lo[2 * H_ * H_];
__device__ __nv_bfloat16 g_Wot_hi[H_ * H_],     g_Wot_lo[H_ * H_];

// ---------------- PTX helpers ----------------
__device__ __forceinline__ unsigned f2tf(float x) {
    unsigned u; asm("cvt.rna.tf32.f32 %0, %1;" : "=r"(u) : "f"(x)); return u;
}
__device__ __forceinline__ void mma8(float& d0, float& d1, float& d2, float& d3,
                                     unsigned a0, unsigned a1, unsigned a2, unsigned a3,
                                     unsigned b0, unsigned b1) {
    asm volatile(
        "mma.sync.aligned.m16n8k8.row.col.f32.tf32.tf32.f32 "
        "{%0,%1,%2,%3}, {%4,%5,%6,%7}, {%8,%9}, {%0,%1,%2,%3};"
        : "+f"(d0), "+f"(d1), "+f"(d2), "+f"(d3)
        : "r"(a0), "r"(a1), "r"(a2), "r"(a3), "r"(b0), "r"(b1));
}
__device__ __forceinline__ void mma_bf16(float* d, const uint32_t* a,
                                         uint32_t b0, uint32_t b1) {
    asm volatile(
        "mma.sync.aligned.m16n8k16.row.col.f32.bf16.bf16.f32 "
        "{%0,%1,%2,%3}, {%4,%5,%6,%7}, {%8,%9}, {%0,%1,%2,%3};"
        : "+f"(d[0]), "+f"(d[1]), "+f"(d[2]), "+f"(d[3])
        : "r"(a[0]), "r"(a[1]), "r"(a[2]), "r"(a[3]), "r"(b0), "r"(b1));
}
__device__ __forceinline__ void ldsm4(uint32_t* r, uint32_t addr) {
    asm volatile("ldmatrix.sync.aligned.m8n8.x4.shared.b16 {%0,%1,%2,%3}, [%4];"
        : "=r"(r[0]), "=r"(r[1]), "=r"(r[2]), "=r"(r[3]) : "r"(addr));
}
__device__ __forceinline__ void cp16(void* smem_dst, const void* gmem_src) {
    unsigned s = (unsigned)__cvta_generic_to_shared(smem_dst);
    asm volatile("cp.async.cg.shared.global [%0], [%1], 16;" :: "r"(s), "l"(gmem_src));
}
__device__ __forceinline__ uint32_t smem_u32(const void* p) {
    uint32_t a;
    asm("{ .reg .u64 t; cvta.to.shared.u64 t, %1; cvt.u32.u64 %0, t; }" : "=r"(a) : "l"(p));
    return a;
}

// ---------------- preprocessing kernels ----------------
__global__ __launch_bounds__(256) void split_f4(
    const float* __restrict__ src, __nv_bfloat16* __restrict__ hi,
    __nv_bfloat16* __restrict__ lo, int n4)
{
    int i = blockIdx.x * blockDim.x + threadIdx.x;
    if (i >= n4) return;
    float4 v = ((const float4*)src)[i];
    __nv_bfloat16 h0 = __float2bfloat16_rn(v.x), h1 = __float2bfloat16_rn(v.y);
    __nv_bfloat16 h2 = __float2bfloat16_rn(v.z), h3 = __float2bfloat16_rn(v.w);
    __nv_bfloat16 l0 = __float2bfloat16_rn(v.x - __bfloat162float(h0));
    __nv_bfloat16 l1 = __float2bfloat16_rn(v.y - __bfloat162float(h1));
    __nv_bfloat16 l2 = __float2bfloat16_rn(v.z - __bfloat162float(h2));
    __nv_bfloat16 l3 = __float2bfloat16_rn(v.w - __bfloat162float(h3));
    ((__nv_bfloat162*)hi)[2 * i]     = __nv_bfloat162(h0, h1);
    ((__nv_bfloat162*)hi)[2 * i + 1] = __nv_bfloat162(h2, h3);
    ((__nv_bfloat162*)lo)[2 * i]     = __nv_bfloat162(l0, l1);
    ((__nv_bfloat162*)lo)[2 * i + 1] = __nv_bfloat162(l2, l3);
}

// W[K,N] fp32 -> Thi/Tlo[N,K] bf16 (transpose + split)
__global__ __launch_bounds__(256) void transpose_split(
    const float* __restrict__ W, __nv_bfloat16* __restrict__ Thi,
    __nv_bfloat16* __restrict__ Tlo, int K, int N)
{
    __shared__ float ts[32][33];
    const int n0 = blockIdx.x * 32, k0 = blockIdx.y * 32;
    const int tx = threadIdx.x, ty = threadIdx.y;
#pragma unroll
    for (int i = 0; i < 4; i++)
        ts[ty + 8 * i][tx] = W[(size_t)(k0 + ty + 8 * i) * N + n0 + tx];
    __syncthreads();
#pragma unroll
    for (int i = 0; i < 4; i++) {
        float v = ts[tx][ty + 8 * i];
        __nv_bfloat16 h = __float2bfloat16_rn(v);
        __nv_bfloat16 l = __float2bfloat16_rn(v - __bfloat162float(h));
        Thi[(size_t)(n0 + ty + 8 * i) * K + k0 + tx] = h;
        Tlo[(size_t)(n0 + ty + 8 * i) * K + k0 + tx] = l;
    }
}

// ---------------- split-bf16 mma.sync GEMM ----------------
// C[M,N] = (Ahi+Alo)[M,K] @ (Bhi+Blo)^T, B stored K-major [N,K].
// CTA 128x128, K-tile 32, 8 warps (2x4), warp tile 64x32, m16n8k16.
// smem rows: 32 bf16 + 8 pad = 80 B stride (conflict-free LDSM phases).
// Layout per stage: [Ahi 10240][Alo 10240][Bhi 10240][Blo 10240]; 2 stages.
#define GR_S 80                       // row stride bytes
#define GARR 10240                    // one operand tile
#define GSTG 40960                    // one stage
#define GS_SMEM (2 * GSTG)            // 81920

__global__ __launch_bounds__(256, 2) void gemm_bf16s(
    const __nv_bfloat16* __restrict__ Ahi, const __nv_bfloat16* __restrict__ Alo,
    const __nv_bfloat16* __restrict__ Bhi, const __nv_bfloat16* __restrict__ Blo,
    float* __restrict__ C, int M, int N, int K)
{
    extern __shared__ char smem[];
    const uint32_t sb = smem_u32(smem);
    const int tid = threadIdx.x, lane = tid & 31, wid = tid >> 5;
    const int bm = blockIdx.y * 128, bn = blockIdx.x * 128;
    const int wm = (wid & 1) * 64, wn = (wid >> 1) * 32;

    // load mapping: 2 chunks of 16B per row per array per thread
    const int lrow = tid >> 1, cb = (tid & 1) * 2;
    const __nv_bfloat16* src0 = Ahi + (size_t)(bm + lrow) * K + cb * 8;
    const __nv_bfloat16* src1 = Alo + (size_t)(bm + lrow) * K + cb * 8;
    const __nv_bfloat16* src2 = Bhi + (size_t)(bn + lrow) * K + cb * 8;
    const __nv_bfloat16* src3 = Blo + (size_t)(bn + lrow) * K + cb * 8;
    const int sdst = lrow * GR_S + cb * 16;

    // ldmatrix lane->address pieces
    const int rowA = (lane & 7) + ((lane >> 3) & 1) * 8;   // A/mat row
    const int kbA  = ((lane >> 4) & 1) * 16;               // A k-chunk byte
    const int rowB = (lane & 7) + ((lane >> 4) & 1) * 8;   // B n-row
    const int kbB  = ((lane >> 3) & 1) * 16;               // B k-chunk byte
    const uint32_t aOff  = (uint32_t)((wm + rowA) * GR_S + kbA);
    const uint32_t bOff  = (uint32_t)(2 * GARR + (wn + rowB) * GR_S + kbB);

    float acc[4][4][4];
#pragma unroll
    for (int i = 0; i < 4; i++)
#pragma unroll
        for (int j = 0; j < 4; j++)
#pragma unroll
            for (int r = 0; r < 4; r++) acc[i][j][r] = 0.0f;

    const int NT = K / 32;

    // prologue: stage 0
    {
        char* sd = smem;
#pragma unroll
        for (int c = 0; c < 2; c++) {
            cp16(sd + sdst + c * 16,             src0 + c * 8);
            cp16(sd + GARR + sdst + c * 16,      src1 + c * 8);
            cp16(sd + 2 * GARR + sdst + c * 16,  src2 + c * 8);
            cp16(sd + 3 * GARR + sdst + c * 16,  src3 + c * 8);
        }
        asm volatile("cp.async.commit_group;");
    }

    for (int t = 0; t < NT; t++) {
        asm volatile("cp.async.wait_group 0;");
        __syncthreads();

        if (t + 1 < NT) {
            const int k0 = (t + 1) * 32;
            char* sd = smem + ((t + 1) & 1) * GSTG;
#pragma unroll
            for (int c = 0; c < 2; c++) {
                cp16(sd + sdst + c * 16,            src0 + k0 + c * 8);
                cp16(sd + GARR + sdst + c * 16,     src1 + k0 + c * 8);
                cp16(sd + 2 * GARR + sdst + c * 16, src2 + k0 + c * 8);
                cp16(sd + 3 * GARR + sdst + c * 16, src3 + k0 + c * 8);
            }
            asm volatile("cp.async.commit_group;");
        }

        const uint32_t sA = sb + (t & 1) * GSTG;
#pragma unroll
        for (int ks = 0; ks < 2; ks++) {
            uint32_t ah[4][4], bh2[2][4], bl2[2][4];
#pragma unroll
            for (int im = 0; im < 4; im++)
                ldsm4(ah[im], sA + aOff + im * 16 * GR_S + ks * 32);
#pragma unroll
            for (int jg = 0; jg < 2; jg++) {
                ldsm4(bh2[jg], sA + bOff + jg * 16 * GR_S + ks * 32);
                ldsm4(bl2[jg], sA + GARR + bOff + jg * 16 * GR_S + ks * 32);
            }
            // hi*hi + hi*lo
#pragma unroll
            for (int im = 0; im < 4; im++)
#pragma unroll
                for (int jn = 0; jn < 4; jn++) {
                    const uint32_t* bh = bh2[jn >> 1];
                    const uint32_t* bl = bl2[jn >> 1];
                    const int s = (jn & 1) * 2;
                    mma_bf16(acc[im][jn], ah[im], bh[s], bh[s + 1]);
                    mma_bf16(acc[im][jn], ah[im], bl[s], bl[s + 1]);
                }
            // lo*hi
            uint32_t al[4][4];
#pragma unroll
            for (int im = 0; im < 4; im++)
                ldsm4(al[im], sA + GARR + aOff + im * 16 * GR_S + ks * 32);
#pragma unroll
            for (int im = 0; im < 4; im++)
#pragma unroll
                for (int jn = 0; jn < 4; jn++) {
                    const uint32_t* bh = bh2[jn >> 1];
                    const int s = (jn & 1) * 2;
                    mma_bf16(acc[im][jn], al[im], bh[s], bh[s + 1]);
                }
        }
        __syncthreads();
    }

    // epilogue
    const int er = (lane >> 2), ec = 2 * (lane & 3);
#pragma unroll
    for (int im = 0; im < 4; im++)
#pragma unroll
        for (int jn = 0; jn < 4; jn++) {
            const int row = bm + wm + im * 16 + er;
            const int col = bn + wn + jn * 8 + ec;
            *(float2*)&C[(size_t)row * N + col] =
                make_float2(acc[im][jn][0], acc[im][jn][1]);
            *(float2*)&C[(size_t)(row + 8) * N + col] =
                make_float2(acc[im][jn][2], acc[im][jn][3]);
        }
}

// ---------------- dual-branch flash attention (tf32 mma.sync) ----------------
// Scores are bounded -> no online max: p = exp2(s_log2 - 12); lane-local l.
#define SQ 68
#define SK 72
#define ATTN_SMEM ((2 * 128 * SQ + 2 * 64 * SK) * 4)   // 106496 B

__global__ __launch_bounds__(256, 2) void attn_mma(
    const float* __restrict__ Q, const float* __restrict__ KVs,
    const float* __restrict__ KVl, float* __restrict__ Out,
    const float* __restrict__ p_mixw, const float* __restrict__ p_decay)
{
    extern __shared__ float sm[];
    float* Qs = sm;                  // [128][SQ] tf32 bits (log2 domain)
    float* Ps = sm + 128 * SQ;       // [128][SQ] tf32 bits
    float* Ks = sm + 2 * 128 * SQ;   // [64][SK]  K^T [d][key]
    float* Vs = Ks + 64 * SK;        // [64][SK]  V   [key][d]

    const int tid = threadIdx.x, lane = tid & 31, wid = tid >> 5;
    const int g = lane >> 2, tg = lane & 3;
    const int q0 = blockIdx.x * 128;
    const int h = blockIdx.y, b = blockIdx.z;
    const int mw = wid * 16;

    const float alpha   = 1.0f / (1.0f + __expf(-p_mixw[0]));
    const float lambda2 = (1.0f - p_decay[0]) * LOG2E;
    const float wmix[2] = {alpha, 1.0f - alpha};
    const float QSCALE  = 0.125f * LOG2E;

    {
        const int r = tid >> 1, half = tid & 1;
        const float* qb = Q + ((size_t)(b * L_ + q0 + r)) * H_ + h * HD_ + half * 32;
        float* qd = Qs + r * SQ + half * 32;
#pragma unroll
        for (int j = 0; j < 8; j++) {
            float4 v = *(const float4*)(qb + j * 4);
            qd[j * 4 + 0] = __uint_as_float(f2tf(v.x * QSCALE));
            qd[j * 4 + 1] = __uint_as_float(f2tf(v.y * QSCALE));
            qd[j * 4 + 2] = __uint_as_float(f2tf(v.z * QSCALE));
            qd[j * 4 + 3] = __uint_as_float(f2tf(v.w * QSCALE));
        }
    }

    for (int branch = 0; branch < 2; branch++) {
        const float* KV = branch ? KVl : KVs;
        float l0 = 0.0f, l1 = 0.0f;
        float o[8][4];
#pragma unroll
        for (int jn = 0; jn < 8; jn++)
#pragma unroll
            for (int r = 0; r < 4; r++) o[jn][r] = 0.0f;

        for (int t = 0; t < L_ / 64; t++) {
            __syncthreads();
            {
                const int r = tid >> 2, cg = tid & 3;
                const float* kb = KV + ((size_t)(b * L_ + t * 64 + r)) * (2 * H_) + h * HD_;
                const float* vb = kb + H_;
#pragma unroll
                for (int it = 0; it < 4; it++) {
                    const int d0 = (cg + it * 4) * 4;
                    float4 k4 = *(const float4*)(kb + d0);
                    Ks[(d0 + 0) * SK + r] = __uint_as_float(f2tf(k4.x));
                    Ks[(d0 + 1) * SK + r] = __uint_as_float(f2tf(k4.y));
                    Ks[(d0 + 2) * SK + r] = __uint_as_float(f2tf(k4.z));
                    Ks[(d0 + 3) * SK + r] = __uint_as_float(f2tf(k4.w));
                    float4 v4 = *(const float4*)(vb + d0);
                    Vs[r * SK + d0 + 0] = __uint_as_float(f2tf(v4.x));
                    Vs[r * SK + d0 + 1] = __uint_as_float(f2tf(v4.y));
                    Vs[r * SK + d0 + 2] = __uint_as_float(f2tf(v4.z));
                    Vs[r * SK + d0 + 3] = __uint_as_float(f2tf(v4.w));
                }
            }
            __syncthreads();

            // S = Q K^T (log2 units)
            float s[8][4];
#pragma unroll
            for (int jn = 0; jn < 8; jn++)
#pragma unroll
                for (int r = 0; r < 4; r++) s[jn][r] = 0.0f;
#pragma unroll
            for (int ks = 0; ks < 8; ks++) {
                const int k0 = ks * 8;
                const float* qp = Qs + (mw + g) * SQ + k0;
                unsigned a0 = __float_as_uint(qp[tg]);
                unsigned a1 = __float_as_uint(qp[8 * SQ + tg]);
                unsigned a2 = __float_as_uint(qp[tg + 4]);
                unsigned a3 = __float_as_uint(qp[8 * SQ + tg + 4]);
#pragma unroll
                for (int jn = 0; jn < 8; jn++) {
                    const float* kpp = Ks + (k0 + tg) * SK + jn * 8 + g;
                    unsigned b0 = __float_as_uint(kpp[0]);
                    unsigned b1 = __float_as_uint(kpp[4 * SK]);
                    mma8(s[jn][0], s[jn][1], s[jn][2], s[jn][3], a0, a1, a2, a3, b0, b1);
                }
            }

            if (branch == 0) {
                const float r0 = (float)(q0 + mw + g), r1 = r0 + 8.0f;
#pragma unroll
                for (int jn = 0; jn < 8; jn++) {
                    const float c0 = (float)(t * 64 + jn * 8 + 2 * tg), c1 = c0 + 1.0f;
                    s[jn][0] -= fabsf(r0 - c0) * lambda2;
                    s[jn][1] -= fabsf(r0 - c1) * lambda2;
                    s[jn][2] -= fabsf(r1 - c0) * lambda2;
                    s[jn][3] -= fabsf(r1 - c1) * lambda2;
                }
            }

            // p = exp2(s - 12); lane-local l; store P (tf32)
            float* pd = Ps + (mw + g) * SQ;
#pragma unroll
            for (int jn = 0; jn < 8; jn++) {
                const int col = jn * 8 + 2 * tg;
                const float p0 = exp2f(s[jn][0] - 12.0f);
                const float p1 = exp2f(s[jn][1] - 12.0f);
                const float p2 = exp2f(s[jn][2] - 12.0f);
                const float p3 = exp2f(s[jn][3] - 12.0f);
                l0 += p0 + p1; l1 += p2 + p3;
                pd[col]              = __uint_as_float(f2tf(p0));
                pd[col + 1]          = __uint_as_float(f2tf(p1));
                pd[8 * SQ + col]     = __uint_as_float(f2tf(p2));
                pd[8 * SQ + col + 1] = __uint_as_float(f2tf(p3));
            }
            __syncwarp();

            // O += P V
#pragma unroll
            for (int ks = 0; ks < 8; ks++) {
                const int k0 = ks * 8;
                const float* pp = Ps + (mw + g) * SQ + k0;
                unsigned a0 = __float_as_uint(pp[tg]);
                unsigned a1 = __float_as_uint(pp[8 * SQ + tg]);
                unsigned a2 = __float_as_uint(pp[tg + 4]);
                unsigned a3 = __float_as_uint(pp[8 * SQ + tg + 4]);
#pragma unroll
                for (int jn = 0; jn < 8; jn++) {
                    const float* vp = Vs + (k0 + tg) * SK + jn * 8 + g;
                    unsigned b0 = __float_as_uint(vp[0]);
                    unsigned b1 = __float_as_uint(vp[4 * SK]);
                    mma8(o[jn][0], o[jn][1], o[jn][2], o[jn][3], a0, a1, a2, a3, b0, b1);
                }
            }
        }

        l0 += __shfl_xor_sync(0xffffffffu, l0, 1);
        l0 += __shfl_xor_sync(0xffffffffu, l0, 2);
        l1 += __shfl_xor_sync(0xffffffffu, l1, 1);
        l1 += __shfl_xor_sync(0xffffffffu, l1, 2);

        const float w  = wmix[branch];
        const float i0 = w / l0, i1 = w / l1;
        float* ob = Out + ((size_t)(b * L_ + q0 + mw + g)) * H_ + h * HD_;
        if (branch == 0) {
#pragma unroll
            for (int jn = 0; jn < 8; jn++) {
                const int col = jn * 8 + 2 * tg;
                *(float2*)(ob + col)          = make_float2(o[jn][0] * i0, o[jn][1] * i0);
                *(float2*)(ob + 8 * H_ + col) = make_float2(o[jn][2] * i1, o[jn][3] * i1);
            }
        } else {
#pragma unroll
            for (int jn = 0; jn < 8; jn++) {
                const int col = jn * 8 + 2 * tg;
                float2 u0 = *(float2*)(ob + col);
                float2 u1 = *(float2*)(ob + 8 * H_ + col);
                *(float2*)(ob + col)          = make_float2(u0.x + o[jn][0] * i0, u0.y + o[jn][1] * i0);
                *(float2*)(ob + 8 * H_ + col) = make_float2(u1.x + o[jn][2] * i1, u1.y + o[jn][3] * i1);
            }
        }
    }
}

// ---------------------------------------------------------------------------
extern "C" void kernel_launch(void* const* d_in, const int* in_sizes, int n_in,
                              void* d_out, int out_size)
{
    const float* x     = (const float*)d_in[0];
    const float* Wq    = (const float*)d_in[1];
    const float* Wkvs  = (const float*)d_in[2];
    const float* Wkvl  = (const float*)d_in[3];
    const float* Wo    = (const float*)d_in[4];
    const float* mixw  = (const float*)d_in[5];
    const float* decay = (const float*)d_in[6];
    float* out = (float*)d_out;

    float *pQ, *pKVs, *pKVl, *pmix;
    __nv_bfloat16 *xhi, *xlo, *mhi, *mlo;
    __nv_bfloat16 *wqh, *wql, *wsh, *wsl, *wlh, *wll, *woh, *wol;
    cudaGetSymbolAddress((void**)&pQ,   g_Q);
    cudaGetSymbolAddress((void**)&pKVs, g_KVs);
    cudaGetSymbolAddress((void**)&pKVl, g_KVl);
    cudaGetSymbolAddress((void**)&pmix, g_mix);
    cudaGetSymbolAddress((void**)&xhi, g_xhi);  cudaGetSymbolAddress((void**)&xlo, g_xlo);
    cudaGetSymbolAddress((void**)&mhi, g_mhi);  cudaGetSymbolAddress((void**)&mlo, g_mlo);
    cudaGetSymbolAddress((void**)&wqh, g_Wqt_hi); cudaGetSymbolAddress((void**)&wql, g_Wqt_lo);
    cudaGetSymbolAddress((void**)&wsh, g_Wst_hi); cudaGetSymbolAddress((void**)&wsl, g_Wst_lo);
    cudaGetSymbolAddress((void**)&wlh, g_Wlt_hi); cudaGetSymbolAddress((void**)&wll, g_Wlt_lo);
    cudaGetSymbolAddress((void**)&woh, g_Wot_hi); cudaGetSymbolAddress((void**)&wol, g_Wot_lo);

    cudaFuncSetAttribute(gemm_bf16s,
                         cudaFuncAttributeMaxDynamicSharedMemorySize, GS_SMEM);
    cudaFuncSetAttribute(attn_mma,
                         cudaFuncAttributeMaxDynamicSharedMemorySize, ATTN_SMEM);

    // preprocess: split x, transpose+split weights
    split_f4<<<M_ * H_ / 4 / 256, 256>>>(x, xhi, xlo, M_ * H_ / 4);
    transpose_split<<<dim3(H_ / 32, H_ / 32),     dim3(32, 8)>>>(Wq,   wqh, wql, H_, H_);
    transpose_split<<<dim3(2 * H_ / 32, H_ / 32), dim3(32, 8)>>>(Wkvs, wsh, wsl, H_, 2 * H_);
    transpose_split<<<dim3(2 * H_ / 32, H_ / 32), dim3(32, 8)>>>(Wkvl, wlh, wll, H_, 2 * H_);
    transpose_split<<<dim3(H_ / 32, H_ / 32),     dim3(32, 8)>>>(Wo,   woh, wol, H_, H_);

    // projections (split-bf16 mma.sync)
    gemm_bf16s<<<dim3(H_ / 128,     M_ / 128), 256, GS_SMEM>>>(xhi, xlo, wqh, wql, pQ,   M_, H_,     H_);
    gemm_bf16s<<<dim3(2 * H_ / 128, M_ / 128), 256, GS_SMEM>>>(xhi, xlo, wsh, wsl, pKVs, M_, 2 * H_, H_);
    gemm_bf16s<<<dim3(2 * H_ / 128, M_ / 128), 256, GS_SMEM>>>(xhi, xlo, wlh, wll, pKVl, M_, 2 * H_, H_);

    // attention
    attn_mma<<<dim3(L_ / 128, NH_, B_), 256, ATTN_SMEM>>>(pQ, pKVs, pKVl, pmix, mixw, decay);

    // output projection
    split_f4<<<M_ * H_ / 4 / 256, 256>>>(pmix, mhi, mlo, M_ * H_ / 4);
    gemm_bf16s<<<dim3(H_ / 128, M_ / 128), 256, GS_SMEM>>>(mhi, mlo, woh, wol, out, M_, H_, H_);
}

// round 5
// speedup vs baseline: 1.3090x; 1.3090x over previous
#include <cuda_runtime.h>
#include <cuda_bf16.h>
#include <cstdint>

#define B_  4
#define L_  1024
#define H_  1024
#define NH_ 16
#define HD_ 64
#define M_  (B_*L_)   // 4096
#define LOG2E 1.4426950408889634f

// ---------------- scratch (device globals; no runtime alloc) ----------------
__device__ float g_Q  [M_ * H_];        // tf32-rounded
__device__ float g_KVs[M_ * 2 * H_];    // tf32-rounded
__device__ float g_KVl[M_ * 2 * H_];    // tf32-rounded
__device__ float g_mix[M_ * H_];        // tf32-rounded (attn epilogue)
__device__ float g_xr [M_ * H_];        // x rounded to tf32
__device__ float g_Wqt[H_ * H_];        // W^T, tf32-rounded
__device__ float g_Wst[2 * H_ * H_];
__device__ float g_Wlt[2 * H_ * H_];
__device__ float g_Wot[H_ * H_];

// ---------------- PTX helpers ----------------
__device__ __forceinline__ unsigned f2tf(float x) {
    unsigned u; asm("cvt.rna.tf32.f32 %0, %1;" : "=r"(u) : "f"(x)); return u;
}
__device__ __forceinline__ float f2tff(float x) {
    return __uint_as_float(f2tf(x));
}
__device__ __forceinline__ void mma8(float& d0, float& d1, float& d2, float& d3,
                                     unsigned a0, unsigned a1, unsigned a2, unsigned a3,
                                     unsigned b0, unsigned b1) {
    asm volatile(
        "mma.sync.aligned.m16n8k8.row.col.f32.tf32.tf32.f32 "
        "{%0,%1,%2,%3}, {%4,%5,%6,%7}, {%8,%9}, {%0,%1,%2,%3};"
        : "+f"(d0), "+f"(d1), "+f"(d2), "+f"(d3)
        : "r"(a0), "r"(a1), "r"(a2), "r"(a3), "r"(b0), "r"(b1));
}
__device__ __forceinline__ void ldsm4(uint32_t* r, uint32_t addr) {
    asm volatile("ldmatrix.sync.aligned.m8n8.x4.shared.b16 {%0,%1,%2,%3}, [%4];"
        : "=r"(r[0]), "=r"(r[1]), "=r"(r[2]), "=r"(r[3]) : "r"(addr));
}
__device__ __forceinline__ void cp16(void* smem_dst, const void* gmem_src) {
    unsigned s = (unsigned)__cvta_generic_to_shared(smem_dst);
    asm volatile("cp.async.cg.shared.global [%0], [%1], 16;" :: "r"(s), "l"(gmem_src));
}
__device__ __forceinline__ uint32_t smem_u32(const void* p) {
    uint32_t a;
    asm("{ .reg .u64 t; cvta.to.shared.u64 t, %1; cvt.u32.u64 %0, t; }" : "=r"(a) : "l"(p));
    return a;
}
#define GSW(o) ((o) ^ (((o) >> 3) & 0x70))   // 128B xor swizzle

// ---------------- preprocessing ----------------
__global__ __launch_bounds__(256) void round_tf32(
    const float* __restrict__ src, float* __restrict__ dst, int n4)
{
    int i = blockIdx.x * blockDim.x + threadIdx.x;
    if (i >= n4) return;
    float4 v = ((const float4*)src)[i];
    v.x = f2tff(v.x); v.y = f2tff(v.y); v.z = f2tff(v.z); v.w = f2tff(v.w);
    ((float4*)dst)[i] = v;
}

// W[K,N] fp32 -> Wt[N,K] tf32
__global__ __launch_bounds__(256) void transpose_round(
    const float* __restrict__ W, float* __restrict__ Wt, int K, int N)
{
    __shared__ float ts[32][33];
    const int n0 = blockIdx.x * 32, k0 = blockIdx.y * 32;
    const int tx = threadIdx.x, ty = threadIdx.y;
#pragma unroll
    for (int i = 0; i < 4; i++)
        ts[ty + 8 * i][tx] = W[(size_t)(k0 + ty + 8 * i) * N + n0 + tx];
    __syncthreads();
#pragma unroll
    for (int i = 0; i < 4; i++)
        Wt[(size_t)(n0 + ty + 8 * i) * K + k0 + tx] = f2tff(ts[tx][ty + 8 * i]);
}

// ---------------- tf32 GEMM, all-ldmatrix fragments ----------------
// C[M,N] = A[M,K] @ B^T (B stored K-major [N,K]); both pre-rounded to tf32.
// CTA 128x128, K-tile 32. smem: A/B tiles 128 rows x 128B, xor-swizzled.
// 8 warps (2M x 4N), warp tile 64x32, m16n8k8.
#define GSTG 32768                  // one stage: A 16KB + B 16KB
#define GS_SMEM (2 * GSTG)          // 65536

__global__ __launch_bounds__(256, 2) void gemm_tf32v(
    const float* __restrict__ A, const float* __restrict__ Bm,
    float* __restrict__ C, int M, int N, int K, int roundOut)
{
    extern __shared__ char smem[];
    const uint32_t sb = smem_u32(smem);
    const int tid = threadIdx.x, lane = tid & 31, wid = tid >> 5;
    const int bm = blockIdx.y * 128, bn = blockIdx.x * 128;
    const int wm = (wid & 1) * 64, wn = (wid >> 1) * 32;

    // cp.async mapping: 2 threads/row, 4 chunks each
    const int lrow = tid >> 1, lch = (tid & 1) * 4;
    const float* Ag = A + (size_t)(bm + lrow) * K + lch * 4;
    const float* Bg = Bm + (size_t)(bn + lrow) * K + lch * 4;
    uint32_t sdst[4];
#pragma unroll
    for (int c = 0; c < 4; c++) sdst[c] = GSW(lrow * 128 + (lch + c) * 16);

    // ldmatrix per-lane address pieces
    const int lm = lane >> 3, lr = lane & 7;
    // A-frag: mat m: row = wm+im*16+(m&1)*8+lr, khalf = m>>1
    const uint32_t aRow = wm + (lm & 1) * 8 + lr;
    const uint32_t aKh  = (lm >> 1) * 16;
    // B-frag: mat m: nrow = wn+(2jp+(m>>1))*8+lr, khalf = m&1
    const uint32_t bRow = wn + (lm >> 1) * 8 + lr;
    const uint32_t bKh  = (lm & 1) * 16;

    float acc[4][4][4];
#pragma unroll
    for (int i = 0; i < 4; i++)
#pragma unroll
        for (int j = 0; j < 4; j++)
#pragma unroll
            for (int r = 0; r < 4; r++) acc[i][j][r] = 0.0f;

    const int NT = K / 32;

    // prologue
#pragma unroll
    for (int c = 0; c < 4; c++) {
        cp16(smem + sdst[c], Ag + c * 4);
        cp16(smem + 16384 + sdst[c], Bg + c * 4);
    }
    asm volatile("cp.async.commit_group;");

    for (int t = 0; t < NT; t++) {
        asm volatile("cp.async.wait_group 0;");
        __syncthreads();

        if (t + 1 < NT) {
            char* sd = smem + ((t + 1) & 1) * GSTG;
            const int k0 = (t + 1) * 32;
#pragma unroll
            for (int c = 0; c < 4; c++) {
                cp16(sd + sdst[c], Ag + k0 + c * 4);
                cp16(sd + 16384 + sdst[c], Bg + k0 + c * 4);
            }
            asm volatile("cp.async.commit_group;");
        }

        const uint32_t sA = sb + (t & 1) * GSTG;
        const uint32_t sB = sA + 16384;
#pragma unroll
        for (int ks = 0; ks < 4; ks++) {
            uint32_t af[4][4], bf[2][4];
#pragma unroll
            for (int im = 0; im < 4; im++)
                ldsm4(af[im], sA + GSW((aRow + im * 16) * 128 + ks * 32 + aKh));
#pragma unroll
            for (int jp = 0; jp < 2; jp++)
                ldsm4(bf[jp], sB + GSW((bRow + jp * 16) * 128 + ks * 32 + bKh));
#pragma unroll
            for (int im = 0; im < 4; im++)
#pragma unroll
                for (int jn = 0; jn < 4; jn++) {
                    const uint32_t* bb = bf[jn >> 1];
                    const int s = (jn & 1) * 2;
                    mma8(acc[im][jn][0], acc[im][jn][1], acc[im][jn][2], acc[im][jn][3],
                         af[im][0], af[im][1], af[im][2], af[im][3], bb[s], bb[s + 1]);
                }
        }
        __syncthreads();
    }

    const int er = lane >> 2, ec = 2 * (lane & 3);
#pragma unroll
    for (int im = 0; im < 4; im++)
#pragma unroll
        for (int jn = 0; jn < 4; jn++) {
            const int row = bm + wm + im * 16 + er;
            const int col = bn + wn + jn * 8 + ec;
            float v0 = acc[im][jn][0], v1 = acc[im][jn][1];
            float v2 = acc[im][jn][2], v3 = acc[im][jn][3];
            if (roundOut) { v0 = f2tff(v0); v1 = f2tff(v1); v2 = f2tff(v2); v3 = f2tff(v3); }
            *(float2*)&C[(size_t)row * N + col] = make_float2(v0, v1);
            *(float2*)&C[(size_t)(row + 8) * N + col] = make_float2(v2, v3);
        }
}

// ---------------- dual-branch flash attention (tf32, all-ldmatrix) ----------------
// Q fragments in registers (loaded once from global, scaled+rounded).
// Ks: [64 key][68w] (dim-contiguous), Vt: [64 d][68w] (key-contiguous),
// Ps: [128 m][68w]. All stride 272B -> conflict-free LDSM.
#define AS_K 0
#define AS_V (64 * 68 * 4)                 // 17408
#define AS_P (2 * 64 * 68 * 4)             // 34816
#define ATTN_SMEM (AS_P + 128 * 68 * 4)    // 69632

__global__ __launch_bounds__(256, 2) void attn_mma(
    const float* __restrict__ Q, const float* __restrict__ KVs,
    const float* __restrict__ KVl, float* __restrict__ Out,
    const float* __restrict__ p_mixw, const float* __restrict__ p_decay)
{
    extern __shared__ char smem[];
    const uint32_t sb = smem_u32(smem);
    const int tid = threadIdx.x, lane = tid & 31, wid = tid >> 5;
    const int g = lane >> 2, tg = lane & 3;
    const int q0 = blockIdx.x * 128;
    const int h = blockIdx.y, b = blockIdx.z;
    const int mw = wid * 16;

    const float alpha   = 1.0f / (1.0f + __expf(-p_mixw[0]));
    const float lambda2 = (1.0f - p_decay[0]) * LOG2E;
    const float wmix[2] = {alpha, 1.0f - alpha};
    const float QSCALE  = 0.125f * LOG2E;

    // ldmatrix per-lane address pieces
    const int lm = lane >> 3, lr = lane & 7;
    // B-frags (K and Vt): mat m: row = (2jp+(m>>1))*8+lr, khalf = m&1
    const uint32_t bRow = (uint32_t)((lm >> 1) * 8 + lr);
    const uint32_t bKh  = (uint32_t)((lm & 1) * 16);
    // A-frag (P): mat m: row = mw+(m&1)*8+lr, khalf = m>>1
    const uint32_t pRow = (uint32_t)(mw + (lm & 1) * 8 + lr);
    const uint32_t pKh  = (uint32_t)((lm >> 1) * 16);

    // ---- Q fragments in registers (once) ----
    unsigned qa[8][4];
    {
        const float* q0p = Q + ((size_t)(b * L_ + q0 + mw + g)) * H_ + h * HD_;
        const float* q1p = q0p + (size_t)8 * H_;
#pragma unroll
        for (int ks = 0; ks < 8; ks++) {
            const int d0 = ks * 8 + tg;
            qa[ks][0] = f2tf(q0p[d0] * QSCALE);
            qa[ks][1] = f2tf(q1p[d0] * QSCALE);
            qa[ks][2] = f2tf(q0p[d0 + 4] * QSCALE);
            qa[ks][3] = f2tf(q1p[d0 + 4] * QSCALE);
        }
    }

    // tile-load mapping
    const int krow = tid >> 2;          // 0..63 (key row)
    const int kc0  = tid & 3;           // chunk group

    for (int branch = 0; branch < 2; branch++) {
        const float* KV = branch ? KVl : KVs;
        float l0 = 0.0f, l1 = 0.0f;
        float o[8][4];
#pragma unroll
        for (int jn = 0; jn < 8; jn++)
#pragma unroll
            for (int r = 0; r < 4; r++) o[jn][r] = 0.0f;

        for (int t = 0; t < L_ / 64; t++) {
            __syncthreads();
            // ---- load K [key][dim] contiguous, V transposed -> Vt [d][key] ----
            {
                const float* kb = KV + ((size_t)(b * L_ + t * 64 + krow)) * (2 * H_) + h * HD_;
                const float* vb = kb + H_;
                char* ksm = smem + AS_K + krow * 272;
                char* vsm = smem + AS_V;
#pragma unroll
                for (int c = 0; c < 4; c++) {
                    const int ch = kc0 + c * 4;            // 0..15
                    float4 k4 = *(const float4*)(kb + ch * 4);
                    *(float4*)(ksm + ch * 16) = k4;
                    float4 v4 = *(const float4*)(vb + ch * 4);
                    ((float*)(vsm + (ch * 4 + 0) * 272))[krow] = v4.x;
                    ((float*)(vsm + (ch * 4 + 1) * 272))[krow] = v4.y;
                    ((float*)(vsm + (ch * 4 + 2) * 272))[krow] = v4.z;
                    ((float*)(vsm + (ch * 4 + 3) * 272))[krow] = v4.w;
                }
            }
            __syncthreads();

            // ---- S = Q K^T ----
            float s[8][4];
#pragma unroll
            for (int jn = 0; jn < 8; jn++)
#pragma unroll
                for (int r = 0; r < 4; r++) s[jn][r] = 0.0f;
#pragma unroll
            for (int ks = 0; ks < 8; ks++) {
                uint32_t bf[4][4];
#pragma unroll
                for (int jp = 0; jp < 4; jp++)
                    ldsm4(bf[jp], sb + AS_K + (bRow + jp * 16) * 272 + ks * 32 + bKh);
#pragma unroll
                for (int jn = 0; jn < 8; jn++) {
                    const uint32_t* bb = bf[jn >> 1];
                    const int sidx = (jn & 1) * 2;
                    mma8(s[jn][0], s[jn][1], s[jn][2], s[jn][3],
                         qa[ks][0], qa[ks][1], qa[ks][2], qa[ks][3], bb[sidx], bb[sidx + 1]);
                }
            }

            if (branch == 0) {
                const float r0 = (float)(q0 + mw + g), r1 = r0 + 8.0f;
#pragma unroll
                for (int jn = 0; jn < 8; jn++) {
                    const float c0 = (float)(t * 64 + jn * 8 + 2 * tg), c1 = c0 + 1.0f;
                    s[jn][0] -= fabsf(r0 - c0) * lambda2;
                    s[jn][1] -= fabsf(r0 - c1) * lambda2;
                    s[jn][2] -= fabsf(r1 - c0) * lambda2;
                    s[jn][3] -= fabsf(r1 - c1) * lambda2;
                }
            }

            // ---- p = exp2(s - 12); lane-local l; store P to Ps ----
            float* pd = (float*)(smem + AS_P + (mw + g) * 272);
#pragma unroll
            for (int jn = 0; jn < 8; jn++) {
                const int col = jn * 8 + 2 * tg;
                const float p0 = exp2f(s[jn][0] - 12.0f);
                const float p1 = exp2f(s[jn][1] - 12.0f);
                const float p2 = exp2f(s[jn][2] - 12.0f);
                const float p3 = exp2f(s[jn][3] - 12.0f);
                l0 += p0 + p1; l1 += p2 + p3;
                *(float2*)(pd + col) = make_float2(f2tff(p0), f2tff(p1));
                *(float2*)(pd + 8 * 68 + col) = make_float2(f2tff(p2), f2tff(p3));
            }
            __syncwarp();   // P rows are warp-private

            // ---- O += P V ----
#pragma unroll
            for (int ks = 0; ks < 8; ks++) {
                uint32_t pf[4], vf[4][4];
                ldsm4(pf, sb + AS_P + pRow * 272 + ks * 32 + pKh);
#pragma unroll
                for (int jp = 0; jp < 4; jp++)
                    ldsm4(vf[jp], sb + AS_V + (bRow + jp * 16) * 272 + ks * 32 + bKh);
#pragma unroll
                for (int jn = 0; jn < 8; jn++) {
                    const uint32_t* bb = vf[jn >> 1];
                    const int sidx = (jn & 1) * 2;
                    mma8(o[jn][0], o[jn][1], o[jn][2], o[jn][3],
                         pf[0], pf[1], pf[2], pf[3], bb[sidx], bb[sidx + 1]);
                }
            }
        }

        l0 += __shfl_xor_sync(0xffffffffu, l0, 1);
        l0 += __shfl_xor_sync(0xffffffffu, l0, 2);
        l1 += __shfl_xor_sync(0xffffffffu, l1, 1);
        l1 += __shfl_xor_sync(0xffffffffu, l1, 2);

        const float w  = wmix[branch];
        const float i0 = w / l0, i1 = w / l1;
        float* ob = Out + ((size_t)(b * L_ + q0 + mw + g)) * H_ + h * HD_;
        if (branch == 0) {
#pragma unroll
            for (int jn = 0; jn < 8; jn++) {
                const int col = jn * 8 + 2 * tg;
                *(float2*)(ob + col) = make_float2(o[jn][0] * i0, o[jn][1] * i0);
                *(float2*)(ob + 8 * H_ + col) = make_float2(o[jn][2] * i1, o[jn][3] * i1);
            }
        } else {
            // mix + round to tf32 (A operand of the final GEMM)
#pragma unroll
            for (int jn = 0; jn < 8; jn++) {
                const int col = jn * 8 + 2 * tg;
                float2 u0 = *(float2*)(ob + col);
                float2 u1 = *(float2*)(ob + 8 * H_ + col);
                *(float2*)(ob + col) =
                    make_float2(f2tff(u0.x + o[jn][0] * i0), f2tff(u0.y + o[jn][1] * i0));
                *(float2*)(ob + 8 * H_ + col) =
                    make_float2(f2tff(u1.x + o[jn][2] * i1), f2tff(u1.y + o[jn][3] * i1));
            }
        }
    }
}

// ---------------------------------------------------------------------------
extern "C" void kernel_launch(void* const* d_in, const int* in_sizes, int n_in,
                              void* d_out, int out_size)
{
    const float* x     = (const float*)d_in[0];
    const float* Wq    = (const float*)d_in[1];
    const float* Wkvs  = (const float*)d_in[2];
    const float* Wkvl  = (const float*)d_in[3];
    const float* Wo    = (const float*)d_in[4];
    const float* mixw  = (const float*)d_in[5];
    const float* decay = (const float*)d_in[6];
    float* out = (float*)d_out;

    float *pQ, *pKVs, *pKVl, *pmix, *pxr, *pwq, *pws, *pwl, *pwo;
    cudaGetSymbolAddress((void**)&pQ,   g_Q);
    cudaGetSymbolAddress((void**)&pKVs, g_KVs);
    cudaGetSymbolAddress((void**)&pKVl, g_KVl);
    cudaGetSymbolAddress((void**)&pmix, g_mix);
    cudaGetSymbolAddress((void**)&pxr,  g_xr);
    cudaGetSymbolAddress((void**)&pwq,  g_Wqt);
    cudaGetSymbolAddress((void**)&pws,  g_Wst);
    cudaGetSymbolAddress((void**)&pwl,  g_Wlt);
    cudaGetSymbolAddress((void**)&pwo,  g_Wot);

    cudaFuncSetAttribute(gemm_tf32v,
                         cudaFuncAttributeMaxDynamicSharedMemorySize, GS_SMEM);
    cudaFuncSetAttribute(attn_mma,
                         cudaFuncAttributeMaxDynamicSharedMemorySize, ATTN_SMEM);

    // preprocess
    round_tf32<<<M_ * H_ / 4 / 256, 256>>>(x, pxr, M_ * H_ / 4);
    transpose_round<<<dim3(H_ / 32, H_ / 32),     dim3(32, 8)>>>(Wq,   pwq, H_, H_);
    transpose_round<<<dim3(2 * H_ / 32, H_ / 32), dim3(32, 8)>>>(Wkvs, pws, H_, 2 * H_);
    transpose_round<<<dim3(2 * H_ / 32, H_ / 32), dim3(32, 8)>>>(Wkvl, pwl, H_, 2 * H_);
    transpose_round<<<dim3(H_ / 32, H_ / 32),     dim3(32, 8)>>>(Wo,   pwo, H_, H_);

    // projections (outputs rounded to tf32 for the attention stage)
    gemm_tf32v<<<dim3(H_ / 128,     M_ / 128), 256, GS_SMEM>>>(pxr, pwq, pQ,   M_, H_,     H_, 1);
    gemm_tf32v<<<dim3(2 * H_ / 128, M_ / 128), 256, GS_SMEM>>>(pxr, pws, pKVs, M_, 2 * H_, H_, 1);
    gemm_tf32v<<<dim3(2 * H_ / 128, M_ / 128), 256, GS_SMEM>>>(pxr, pwl, pKVl, M_, 2 * H_, H_, 1);

    // attention (writes tf32-rounded mix)
    attn_mma<<<dim3(L_ / 128, NH_, B_), 256, ATTN_SMEM>>>(pQ, pKVs, pKVl, pmix, mixw, decay);

    // output projection (full-precision output)
    gemm_tf32v<<<dim3(H_ / 128, M_ / 128), 256, GS_SMEM>>>(pmix, pwo, out, M_, H_, H_, 0);
}

// round 6
// speedup vs baseline: 1.3607x; 1.0395x over previous
#include <cuda_runtime.h>
#include <cuda_bf16.h>
#include <cstdint>

#define B_  4
#define L_  1024
#define H_  1024
#define NH_ 16
#define HD_ 64
#define M_  (B_*L_)   // 4096
#define LOG2E 1.4426950408889634f

// ---------------- scratch (device globals; no runtime alloc) ----------------
__device__ float g_Q  [M_ * H_];        // tf32-rounded
__device__ float g_KVs[M_ * 2 * H_];    // tf32-rounded
__device__ float g_KVl[M_ * 2 * H_];
__device__ float g_Vts[B_ * NH_ * HD_ * L_];   // V^T short: [b*NH+h][d][L]
__device__ float g_Vtl[B_ * NH_ * HD_ * L_];   // V^T long
__device__ float g_mix[M_ * H_];        // tf32-rounded
__device__ float g_xr [M_ * H_];
__device__ float g_Wqt[H_ * H_];
__device__ float g_Wst[2 * H_ * H_];
__device__ float g_Wlt[2 * H_ * H_];
__device__ float g_Wot[H_ * H_];

// ---------------- PTX helpers ----------------
__device__ __forceinline__ unsigned f2tf(float x) {
    unsigned u; asm("cvt.rna.tf32.f32 %0, %1;" : "=r"(u) : "f"(x)); return u;
}
__device__ __forceinline__ float f2tff(float x) { return __uint_as_float(f2tf(x)); }
__device__ __forceinline__ float ex2(float x) {
    float y; asm("ex2.approx.ftz.f32 %0, %1;" : "=f"(y) : "f"(x)); return y;
}
__device__ __forceinline__ void mma8(float& d0, float& d1, float& d2, float& d3,
                                     unsigned a0, unsigned a1, unsigned a2, unsigned a3,
                                     unsigned b0, unsigned b1) {
    asm volatile(
        "mma.sync.aligned.m16n8k8.row.col.f32.tf32.tf32.f32 "
        "{%0,%1,%2,%3}, {%4,%5,%6,%7}, {%8,%9}, {%0,%1,%2,%3};"
        : "+f"(d0), "+f"(d1), "+f"(d2), "+f"(d3)
        : "r"(a0), "r"(a1), "r"(a2), "r"(a3), "r"(b0), "r"(b1));
}
__device__ __forceinline__ void ldsm4(uint32_t* r, uint32_t addr) {
    asm volatile("ldmatrix.sync.aligned.m8n8.x4.shared.b16 {%0,%1,%2,%3}, [%4];"
        : "=r"(r[0]), "=r"(r[1]), "=r"(r[2]), "=r"(r[3]) : "r"(addr));
}
__device__ __forceinline__ void cp16(void* smem_dst, const void* gmem_src) {
    unsigned s = (unsigned)__cvta_generic_to_shared(smem_dst);
    asm volatile("cp.async.cg.shared.global [%0], [%1], 16;" :: "r"(s), "l"(gmem_src));
}
__device__ __forceinline__ uint32_t smem_u32(const void* p) {
    uint32_t a;
    asm("{ .reg .u64 t; cvta.to.shared.u64 t, %1; cvt.u32.u64 %0, t; }" : "=r"(a) : "l"(p));
    return a;
}
#define GSW(o) ((o) ^ (((o) >> 3) & 0x70))   // 128B xor swizzle

// ---------------- preprocessing ----------------
__global__ __launch_bounds__(256) void round_tf32(
    const float* __restrict__ src, float* __restrict__ dst, int n4)
{
    int i = blockIdx.x * blockDim.x + threadIdx.x;
    if (i >= n4) return;
    float4 v = ((const float4*)src)[i];
    v.x = f2tff(v.x); v.y = f2tff(v.y); v.z = f2tff(v.z); v.w = f2tff(v.w);
    ((float4*)dst)[i] = v;
}

// fused weight transpose+round: z selects matrix (0:Wq 1:Wkvs 2:Wkvl 3:Wo)
__global__ __launch_bounds__(256) void wtrans(
    const float* __restrict__ Wq, const float* __restrict__ Ws,
    const float* __restrict__ Wl, const float* __restrict__ Wo,
    float* __restrict__ Tq, float* __restrict__ Ts,
    float* __restrict__ Tl, float* __restrict__ To)
{
    const int z = blockIdx.z;
    const float* W = (z == 0) ? Wq : (z == 1) ? Ws : (z == 2) ? Wl : Wo;
    float* T = (z == 0) ? Tq : (z == 1) ? Ts : (z == 2) ? Tl : To;
    const int N = (z == 1 || z == 2) ? 2 * H_ : H_;
    const int n0 = blockIdx.x * 32, k0 = blockIdx.y * 32;
    if (n0 >= N) return;
    __shared__ float ts[32][33];
    const int tx = threadIdx.x, ty = threadIdx.y;
#pragma unroll
    for (int i = 0; i < 4; i++)
        ts[ty + 8 * i][tx] = W[(size_t)(k0 + ty + 8 * i) * N + n0 + tx];
    __syncthreads();
#pragma unroll
    for (int i = 0; i < 4; i++)
        T[(size_t)(n0 + ty + 8 * i) * H_ + k0 + tx] = f2tff(ts[tx][ty + 8 * i]);
}

// V^T builder: both branches in one launch. z: branch*64 + b*NH+h
__global__ __launch_bounds__(256) void vtrans(
    const float* __restrict__ KVs, const float* __restrict__ KVl,
    float* __restrict__ Vts, float* __restrict__ Vtl)
{
    const int z = blockIdx.z;
    const int branch = z >> 6, bh = z & 63;
    const int b = bh >> 4, h = bh & 15;
    const float* KV = branch ? KVl : KVs;
    float* Vt = branch ? Vtl : Vts;
    __shared__ float ts[32][33];
    const int l0 = blockIdx.x * 32, d0 = blockIdx.y * 32;
    const int tx = threadIdx.x, ty = threadIdx.y;
#pragma unroll
    for (int i = 0; i < 4; i++)
        ts[ty + 8 * i][tx] =
            KV[(size_t)(b * L_ + l0 + ty + 8 * i) * (2 * H_) + H_ + h * HD_ + d0 + tx];
    __syncthreads();
#pragma unroll
    for (int i = 0; i < 4; i++)
        Vt[((size_t)(bh * HD_ + d0 + ty + 8 * i)) * L_ + l0 + tx] = ts[tx][ty + 8 * i];
}

// ---------------- tf32 GEMM, all-ldmatrix fragments ----------------
#define GSTG 32768
#define GS_SMEM (2 * GSTG)

__global__ __launch_bounds__(256, 2) void gemm_tf32v(
    const float* __restrict__ A, const float* __restrict__ Bm,
    float* __restrict__ C, int M, int N, int K, int roundOut)
{
    extern __shared__ char smem[];
    const uint32_t sb = smem_u32(smem);
    const int tid = threadIdx.x, lane = tid & 31, wid = tid >> 5;
    const int bm = blockIdx.y * 128, bn = blockIdx.x * 128;
    const int wm = (wid & 1) * 64, wn = (wid >> 1) * 32;

    const int lrow = tid >> 1, lch = (tid & 1) * 4;
    const float* Ag = A + (size_t)(bm + lrow) * K + lch * 4;
    const float* Bg = Bm + (size_t)(bn + lrow) * K + lch * 4;
    uint32_t sdst[4];
#pragma unroll
    for (int c = 0; c < 4; c++) sdst[c] = GSW(lrow * 128 + (lch + c) * 16);

    const int lm = lane >> 3, lr = lane & 7;
    const uint32_t aRow = wm + (lm & 1) * 8 + lr;
    const uint32_t aKh  = (lm >> 1) * 16;
    const uint32_t bRow = wn + (lm >> 1) * 8 + lr;
    const uint32_t bKh  = (lm & 1) * 16;

    float acc[4][4][4];
#pragma unroll
    for (int i = 0; i < 4; i++)
#pragma unroll
        for (int j = 0; j < 4; j++)
#pragma unroll
            for (int r = 0; r < 4; r++) acc[i][j][r] = 0.0f;

    const int NT = K / 32;
#pragma unroll
    for (int c = 0; c < 4; c++) {
        cp16(smem + sdst[c], Ag + c * 4);
        cp16(smem + 16384 + sdst[c], Bg + c * 4);
    }
    asm volatile("cp.async.commit_group;");

    for (int t = 0; t < NT; t++) {
        asm volatile("cp.async.wait_group 0;");
        __syncthreads();
        if (t + 1 < NT) {
            char* sd = smem + ((t + 1) & 1) * GSTG;
            const int k0 = (t + 1) * 32;
#pragma unroll
            for (int c = 0; c < 4; c++) {
                cp16(sd + sdst[c], Ag + k0 + c * 4);
                cp16(sd + 16384 + sdst[c], Bg + k0 + c * 4);
            }
            asm volatile("cp.async.commit_group;");
        }
        const uint32_t sA = sb + (t & 1) * GSTG;
        const uint32_t sB = sA + 16384;
#pragma unroll
        for (int ks = 0; ks < 4; ks++) {
            uint32_t af[4][4], bf[2][4];
#pragma unroll
            for (int im = 0; im < 4; im++)
                ldsm4(af[im], sA + GSW((aRow + im * 16) * 128 + ks * 32 + aKh));
#pragma unroll
            for (int jp = 0; jp < 2; jp++)
                ldsm4(bf[jp], sB + GSW((bRow + jp * 16) * 128 + ks * 32 + bKh));
#pragma unroll
            for (int im = 0; im < 4; im++)
#pragma unroll
                for (int jn = 0; jn < 4; jn++) {
                    const uint32_t* bb = bf[jn >> 1];
                    const int s = (jn & 1) * 2;
                    mma8(acc[im][jn][0], acc[im][jn][1], acc[im][jn][2], acc[im][jn][3],
                         af[im][0], af[im][1], af[im][2], af[im][3], bb[s], bb[s + 1]);
                }
        }
        __syncthreads();
    }

    const int er = lane >> 2, ec = 2 * (lane & 3);
#pragma unroll
    for (int im = 0; im < 4; im++)
#pragma unroll
        for (int jn = 0; jn < 4; jn++) {
            const int row = bm + wm + im * 16 + er;
            const int col = bn + wn + jn * 8 + ec;
            float v0 = acc[im][jn][0], v1 = acc[im][jn][1];
            float v2 = acc[im][jn][2], v3 = acc[im][jn][3];
            if (roundOut) { v0 = f2tff(v0); v1 = f2tff(v1); v2 = f2tff(v2); v3 = f2tff(v3); }
            *(float2*)&C[(size_t)row * N + col] = make_float2(v0, v1);
            *(float2*)&C[(size_t)(row + 8) * N + col] = make_float2(v2, v3);
        }
}

// ---------------- dual-branch flash attention, cp.async pipelined ----------------
// smem: stage s in {0,1}: K [64key][272B] at s*34816, Vt [64d][272B] at +17408.
// P [128m][272B] at 69632. Total 104448 B. 2 CTAs/SM.
#define ATK 17408
#define ASTG 34816
#define AT_P 69632
#define ATTN_SMEM (AT_P + 128 * 272)   // 104448

__global__ __launch_bounds__(256, 2) void attn_mma(
    const float* __restrict__ Q, const float* __restrict__ KVs,
    const float* __restrict__ KVl, const float* __restrict__ Vts,
    const float* __restrict__ Vtl, float* __restrict__ Out,
    const float* __restrict__ p_mixw, const float* __restrict__ p_decay)
{
    extern __shared__ char smem[];
    const uint32_t sb = smem_u32(smem);
    const int tid = threadIdx.x, lane = tid & 31, wid = tid >> 5;
    const int g = lane >> 2, tg = lane & 3;
    const int q0 = blockIdx.x * 128;
    const int h = blockIdx.y, b = blockIdx.z;
    const int bh = b * NH_ + h;
    const int mw = wid * 16;

    const float alpha   = 1.0f / (1.0f + __expf(-p_mixw[0]));
    const float lambda2 = (1.0f - p_decay[0]) * LOG2E;
    const float wmix[2] = {alpha, 1.0f - alpha};
    const float QSCALE  = 0.125f * LOG2E;

    const int lm = lane >> 3, lr = lane & 7;
    const uint32_t bRow = (uint32_t)((lm >> 1) * 8 + lr);
    const uint32_t bKh  = (uint32_t)((lm & 1) * 16);
    const uint32_t pRow = (uint32_t)(mw + (lm & 1) * 8 + lr);
    const uint32_t pKh  = (uint32_t)((lm >> 1) * 16);

    // Q fragments in registers (loaded once)
    unsigned qa[8][4];
    {
        const float* q0p = Q + ((size_t)(b * L_ + q0 + mw + g)) * H_ + h * HD_;
        const float* q1p = q0p + (size_t)8 * H_;
#pragma unroll
        for (int ks = 0; ks < 8; ks++) {
            const int d0 = ks * 8 + tg;
            qa[ks][0] = f2tf(q0p[d0] * QSCALE);
            qa[ks][1] = f2tf(q1p[d0] * QSCALE);
            qa[ks][2] = f2tf(q0p[d0 + 4] * QSCALE);
            qa[ks][3] = f2tf(q1p[d0 + 4] * QSCALE);
        }
    }

    // tile-load mapping: 4 threads/row, 4 chunks each
    const int kr = tid >> 2, c0 = tid & 3;

    // issue cp.async loads for pipeline slot (branch = slot>>4, tile = slot&15)
    auto issue_load = [&](int slot) {
        const int br = slot >> 4, tt = slot & 15;
        const float* Kb = (br ? KVl : KVs) +
            ((size_t)(b * L_ + tt * 64 + kr)) * (2 * H_) + h * HD_;
        const float* Vb = (br ? Vtl : Vts) +
            ((size_t)(bh * HD_ + kr)) * L_ + tt * 64;
        char* stg = smem + (slot & 1) * ASTG;
        char* krow_s = stg + kr * 272;
        char* vrow_s = stg + ATK + kr * 272;
#pragma unroll
        for (int c = 0; c < 4; c++) {
            const int ch = c0 + c * 4;
            cp16(krow_s + ch * 16, Kb + ch * 4);
            cp16(vrow_s + ch * 16, Vb + ch * 4);
        }
        asm volatile("cp.async.commit_group;");
    };

    issue_load(0);

    for (int branch = 0; branch < 2; branch++) {
        float l0 = 0.0f, l1 = 0.0f;
        float o[8][4];
#pragma unroll
        for (int jn = 0; jn < 8; jn++)
#pragma unroll
            for (int r = 0; r < 4; r++) o[jn][r] = 0.0f;

        for (int t = 0; t < 16; t++) {
            const int slot = branch * 16 + t;
            asm volatile("cp.async.wait_group 0;");
            __syncthreads();
            if (slot + 1 < 32) issue_load(slot + 1);

            const uint32_t stK = sb + (slot & 1) * ASTG;
            const uint32_t stV = stK + ATK;

            // ---- S = Q K^T ----
            float s[8][4];
#pragma unroll
            for (int jn = 0; jn < 8; jn++)
#pragma unroll
                for (int r = 0; r < 4; r++) s[jn][r] = 0.0f;
#pragma unroll
            for (int ks = 0; ks < 8; ks++) {
                uint32_t bf[4][4];
#pragma unroll
                for (int jp = 0; jp < 4; jp++)
                    ldsm4(bf[jp], stK + (bRow + jp * 16) * 272 + ks * 32 + bKh);
#pragma unroll
                for (int jn = 0; jn < 8; jn++) {
                    const uint32_t* bb = bf[jn >> 1];
                    const int sidx = (jn & 1) * 2;
                    mma8(s[jn][0], s[jn][1], s[jn][2], s[jn][3],
                         qa[ks][0], qa[ks][1], qa[ks][2], qa[ks][3], bb[sidx], bb[sidx + 1]);
                }
            }

            if (branch == 0) {
                const float r0 = (float)(q0 + mw + g), r1 = r0 + 8.0f;
#pragma unroll
                for (int jn = 0; jn < 8; jn++) {
                    const float c0f = (float)(t * 64 + jn * 8 + 2 * tg), c1f = c0f + 1.0f;
                    s[jn][0] -= fabsf(r0 - c0f) * lambda2;
                    s[jn][1] -= fabsf(r0 - c1f) * lambda2;
                    s[jn][2] -= fabsf(r1 - c0f) * lambda2;
                    s[jn][3] -= fabsf(r1 - c1f) * lambda2;
                }
            }

            // ---- p = exp2(s - 12); lane-local l; store P ----
            float* pd = (float*)(smem + AT_P + (mw + g) * 272);
#pragma unroll
            for (int jn = 0; jn < 8; jn++) {
                const int col = jn * 8 + 2 * tg;
                const float p0 = ex2(s[jn][0] - 12.0f);
                const float p1 = ex2(s[jn][1] - 12.0f);
                const float p2 = ex2(s[jn][2] - 12.0f);
                const float p3 = ex2(s[jn][3] - 12.0f);
                l0 += p0 + p1; l1 += p2 + p3;
                *(float2*)(pd + col) = make_float2(f2tff(p0), f2tff(p1));
                *(float2*)(pd + 8 * 68 + col) = make_float2(f2tff(p2), f2tff(p3));
            }
            __syncwarp();

            // ---- O += P V ----
#pragma unroll
            for (int ks = 0; ks < 8; ks++) {
                uint32_t pf[4], vf[4][4];
                ldsm4(pf, sb + AT_P + pRow * 272 + ks * 32 + pKh);
#pragma unroll
                for (int jp = 0; jp < 4; jp++)
                    ldsm4(vf[jp], stV + (bRow + jp * 16) * 272 + ks * 32 + bKh);
#pragma unroll
                for (int jn = 0; jn < 8; jn++) {
                    const uint32_t* bb = vf[jn >> 1];
                    const int sidx = (jn & 1) * 2;
                    mma8(o[jn][0], o[jn][1], o[jn][2], o[jn][3],
                         pf[0], pf[1], pf[2], pf[3], bb[sidx], bb[sidx + 1]);
                }
            }
        }

        l0 += __shfl_xor_sync(0xffffffffu, l0, 1);
        l0 += __shfl_xor_sync(0xffffffffu, l0, 2);
        l1 += __shfl_xor_sync(0xffffffffu, l1, 1);
        l1 += __shfl_xor_sync(0xffffffffu, l1, 2);

        const float w  = wmix[branch];
        const float i0 = w / l0, i1 = w / l1;
        float* ob = Out + ((size_t)(b * L_ + q0 + mw + g)) * H_ + h * HD_;
        if (branch == 0) {
#pragma unroll
            for (int jn = 0; jn < 8; jn++) {
                const int col = jn * 8 + 2 * tg;
                *(float2*)(ob + col) = make_float2(o[jn][0] * i0, o[jn][1] * i0);
                *(float2*)(ob + 8 * H_ + col) = make_float2(o[jn][2] * i1, o[jn][3] * i1);
            }
        } else {
#pragma unroll
            for (int jn = 0; jn < 8; jn++) {
                const int col = jn * 8 + 2 * tg;
                float2 u0 = *(float2*)(ob + col);
                float2 u1 = *(float2*)(ob + 8 * H_ + col);
                *(float2*)(ob + col) =
                    make_float2(f2tff(u0.x + o[jn][0] * i0), f2tff(u0.y + o[jn][1] * i0));
                *(float2*)(ob + 8 * H_ + col) =
                    make_float2(f2tff(u1.x + o[jn][2] * i1), f2tff(u1.y + o[jn][3] * i1));
            }
        }
    }
}

// ---------------------------------------------------------------------------
extern "C" void kernel_launch(void* const* d_in, const int* in_sizes, int n_in,
                              void* d_out, int out_size)
{
    const float* x     = (const float*)d_in[0];
    const float* Wq    = (const float*)d_in[1];
    const float* Wkvs  = (const float*)d_in[2];
    const float* Wkvl  = (const float*)d_in[3];
    const float* Wo    = (const float*)d_in[4];
    const float* mixw  = (const float*)d_in[5];
    const float* decay = (const float*)d_in[6];
    float* out = (float*)d_out;

    float *pQ, *pKVs, *pKVl, *pVts, *pVtl, *pmix, *pxr, *pwq, *pws, *pwl, *pwo;
    cudaGetSymbolAddress((void**)&pQ,   g_Q);
    cudaGetSymbolAddress((void**)&pKVs, g_KVs);
    cudaGetSymbolAddress((void**)&pKVl, g_KVl);
    cudaGetSymbolAddress((void**)&pVts, g_Vts);
    cudaGetSymbolAddress((void**)&pVtl, g_Vtl);
    cudaGetSymbolAddress((void**)&pmix, g_mix);
    cudaGetSymbolAddress((void**)&pxr,  g_xr);
    cudaGetSymbolAddress((void**)&pwq,  g_Wqt);
    cudaGetSymbolAddress((void**)&pws,  g_Wst);
    cudaGetSymbolAddress((void**)&pwl,  g_Wlt);
    cudaGetSymbolAddress((void**)&pwo,  g_Wot);

    cudaFuncSetAttribute(gemm_tf32v,
                         cudaFuncAttributeMaxDynamicSharedMemorySize, GS_SMEM);
    cudaFuncSetAttribute(attn_mma,
                         cudaFuncAttributeMaxDynamicSharedMemorySize, ATTN_SMEM);

    // preprocess
    round_tf32<<<M_ * H_ / 4 / 256, 256>>>(x, pxr, M_ * H_ / 4);
    wtrans<<<dim3(2 * H_ / 32, H_ / 32, 4), dim3(32, 8)>>>(Wq, Wkvs, Wkvl, Wo,
                                                           pwq, pws, pwl, pwo);

    // projections (outputs tf32-rounded)
    gemm_tf32v<<<dim3(H_ / 128,     M_ / 128), 256, GS_SMEM>>>(pxr, pwq, pQ,   M_, H_,     H_, 1);
    gemm_tf32v<<<dim3(2 * H_ / 128, M_ / 128), 256, GS_SMEM>>>(pxr, pws, pKVs, M_, 2 * H_, H_, 1);
    gemm_tf32v<<<dim3(2 * H_ / 128, M_ / 128), 256, GS_SMEM>>>(pxr, pwl, pKVl, M_, 2 * H_, H_, 1);

    // V^T for both branches
    vtrans<<<dim3(L_ / 32, HD_ / 32, 128), dim3(32, 8)>>>(pKVs, pKVl, pVts, pVtl);

    // attention
    attn_mma<<<dim3(L_ / 128, NH_, B_), 256, ATTN_SMEM>>>(pQ, pKVs, pKVl, pVts, pVtl,
                                                          pmix, mixw, decay);

    // output projection
    gemm_tf32v<<<dim3(H_ / 128, M_ / 128), 256, GS_SMEM>>>(pmix, pwo, out, M_, H_, H_, 0);
}